// round 14
// baseline (speedup 1.0000x reference)
#include <cuda_runtime.h>
#include <cuda_fp16.h>
#include <cstdint>
#include <cstddef>

// Problem constants
#define BB 2
#define FF 42
#define HW 390
#define HH 12
#define HD 64
#define DIM 768
#define TF 21
#define TOPK 5
#define CH 5
#define TS 10
#define NKEY 3900
#define NT 64
#define NTILES 61
#define QT 4
#define NELEM (BB*FF*HW*DIM)      // 25,159,680
#define RHALF 195                 // HW/2 rows per cvt chunk
// 0.125 * log2(e) folded into Q at conversion
#define QSCL 0.18033688011112042f

#define KVSTRIDE 144
#define BUFSZ (128*KVSTRIDE)      // 18432 B per stage
#define NSTAGE 3
#define SMEM_SZ (NSTAGE*BUFSZ + 64)

// fp16 copies of inputs (scratch device globals)
__device__ __half g_qh[NELEM];
__device__ __half g_kh[NELEM];
__device__ __half g_vh[NELEM];
__device__ float  g_qrepr2[2*BB*FF*DIM];   // partial row sums (2 halves)
__device__ float  g_krepr2[2*BB*FF*DIM];
__device__ int    g_sel[BB*FF*TS];

// ---------------------------------------------------------------------------
// PTX helpers (sm_80-level only — target is plain sm_100)
// ---------------------------------------------------------------------------
__device__ __forceinline__ uint32_t s2u(const void* p){
    uint32_t a;
    asm("{ .reg .u64 t; cvta.to.shared.u64 t, %1; cvt.u32.u64 %0, t; }":"=r"(a):"l"(p));
    return a;
}
__device__ __forceinline__ void ldm_x4(uint32_t addr, uint32_t* r){
    asm volatile("ldmatrix.sync.aligned.m8n8.x4.shared.b16 {%0,%1,%2,%3}, [%4];"
        : "=r"(r[0]),"=r"(r[1]),"=r"(r[2]),"=r"(r[3]) : "r"(addr));
}
__device__ __forceinline__ void ldm_x4_t(uint32_t addr, uint32_t* r){
    asm volatile("ldmatrix.sync.aligned.m8n8.x4.trans.shared.b16 {%0,%1,%2,%3}, [%4];"
        : "=r"(r[0]),"=r"(r[1]),"=r"(r[2]),"=r"(r[3]) : "r"(addr));
}
__device__ __forceinline__ void mma16816(float* d, const uint32_t* a,
                                         uint32_t b0, uint32_t b1){
    asm volatile("mma.sync.aligned.m16n8k16.row.col.f32.f16.f16.f32 "
        "{%0,%1,%2,%3}, {%4,%5,%6,%7}, {%8,%9}, {%0,%1,%2,%3};"
        : "+f"(d[0]),"+f"(d[1]),"+f"(d[2]),"+f"(d[3])
        : "r"(a[0]),"r"(a[1]),"r"(a[2]),"r"(a[3]), "r"(b0),"r"(b1));
}
__device__ __forceinline__ float ex2(float x){
    float r; asm("ex2.approx.ftz.f32 %0, %1;" : "=f"(r) : "f"(x)); return r;
}
__device__ __forceinline__ uint32_t h2bits(float lo, float hi){
    __half2 h = __floats2half2_rn(lo, hi);
    return *reinterpret_cast<uint32_t*>(&h);
}
#define CP_ASYNC16(sm, gp) \
    asm volatile("cp.async.cg.shared.global [%0], [%1], 16;" :: "r"(sm), "l"(gp))
#define CP_COMMIT() asm volatile("cp.async.commit_group;" ::: "memory")
#define CP_WAIT1()  asm volatile("cp.async.wait_group 1;" ::: "memory")

// ---------------------------------------------------------------------------
// Kernel 0: fused fp32->fp16 conversion for q,k,v + partial means for q,k
// grid (BB*FF*3, 3, 2): x = bf*3+dimchunk(256 dims), y = 0:q 1:k 2:v,
// z = row half. block = 128. Each thread: 2 adjacent dims, 195 rows.
// ---------------------------------------------------------------------------
__global__ void cvtall_kernel(const float* __restrict__ q,
                              const float* __restrict__ k,
                              const float* __restrict__ v)
{
    int arr = blockIdx.y;
    int rc  = blockIdx.z;
    const float* src = (arr == 0) ? q : (arr == 1) ? k : v;
    __half* dst = (arr == 0) ? g_qh : (arr == 1) ? g_kh : g_vh;
    float scl = (arr == 0) ? QSCL : 1.0f;
    int bf = blockIdx.x / 3;
    int dc = blockIdx.x % 3;
    int d0 = dc * 256 + threadIdx.x * 2;
    size_t base = (size_t)bf * HW * DIM + (size_t)rc * RHALF * DIM + d0;
    float s0 = 0.f, s1 = 0.f;
    #pragma unroll 5
    for (int r = 0; r < RHALF; r++) {
        float2 x = *(const float2*)(src + base + (size_t)r * DIM);
        s0 += x.x; s1 += x.y;
        *(__half2*)(dst + base + (size_t)r * DIM) =
            __floats2half2_rn(x.x * scl, x.y * scl);
    }
    if (arr < 2) {
        float* mdst = arr ? g_krepr2 : g_qrepr2;
        size_t mo = (size_t)(rc * BB * FF + bf) * DIM + d0;
        mdst[mo]     = s0;
        mdst[mo + 1] = s1;
    }
}

// ---------------------------------------------------------------------------
// Kernel 2: sim row + top-k + selection  (sums the two mean partials; sim is
// scaled by a positive constant vs reference -> identical top-k ordering)
// ---------------------------------------------------------------------------
__global__ void sel_kernel(const int* __restrict__ cam)
{
    int bf = blockIdx.x;
    int b = bf / FF, f = bf % FF;
    __shared__ float qs[DIM];
    __shared__ float sim[FF];

    for (int d = threadIdx.x; d < DIM; d += blockDim.x)
        qs[d] = g_qrepr2[bf * DIM + d]
              + g_qrepr2[(BB * FF + bf) * DIM + d];
    __syncthreads();

    for (int g = threadIdx.x; g < FF; g += blockDim.x) {
        const float* kr0 = &g_krepr2[(b * FF + g) * DIM];
        const float* kr1 = &g_krepr2[(BB * FF + b * FF + g) * DIM];
        float s = 0.f;
        #pragma unroll 4
        for (int d = 0; d < DIM; d++) s += qs[d] * (kr0[d] + kr1[d]);
        sim[g] = s;
    }
    __syncthreads();

    if (threadIdx.x == 0) {
        int sel[TS];
        int start = f - 2;
        if (start < 0)  start = 0;
        if (start > 16) start = 16;
        #pragma unroll
        for (int j = 0; j < CH; j++) sel[j] = start + j;

        if (f < TF) {
            #pragma unroll
            for (int j = 0; j < TOPK; j++) sel[CH + j] = cam[f * TOPK + j];
        } else {
            bool used[FF - TF];
            for (int g = 0; g < FF - TF; g++) used[g] = false;
            for (int j = 0; j < TOPK; j++) {
                float best = -3.4e38f; int bi = 0;
                for (int g = 0; g < FF - TF; g++) {
                    if (!used[g] && sim[TF + g] > best) { best = sim[TF + g]; bi = g; }
                }
                used[bi] = true;
                sel[CH + j] = bi + TF;
            }
        }
        for (int j = 0; j < TS; j++) g_sel[bf * TS + j] = sel[j];
    }
}

// ---------------------------------------------------------------------------
// K/V tile stage via cp.async: rows 0..63 = K, 64..127 = V, stride 144B
// ---------------------------------------------------------------------------
__device__ __forceinline__ void stage_kv(uint32_t dstb,
                                         const __half* kh, const __half* vh,
                                         const int* ssel, int kbase, int tid)
{
    #pragma unroll
    for (int it = 0; it < 8; it++) {
        int i = tid + it * 128;
        int r = i >> 3, c = i & 7;
        int kk = kbase + (r & 63);
        if (kk > NKEY - 1) kk = NKEY - 1;
        int fr = kk / HW;
        int g  = ssel[fr];
        const __half* src = (r < 64 ? kh : vh)
            + (size_t)(g * HW + (kk - fr * HW)) * DIM + c * 8;
        CP_ASYNC16(dstb + (uint32_t)(r * KVSTRIDE + c * 16), src);
    }
}

// ---------------------------------------------------------------------------
// Kernel 3: fp16 mma.sync flash attention  (R11 configuration — best measured)
// grid = (QT*HH, BB*FF), block = 128 (4 warps, warp owns 32 q rows)
// 3-stage cp.async ring; 64-key tile processed as two 32-key halves to keep
// register pressure under the 3-CTA/SM cap (launch_bounds 128,3)
// ---------------------------------------------------------------------------
__global__ __launch_bounds__(128, 3)
void attn_kernel(float* __restrict__ out)
{
    extern __shared__ __align__(16) unsigned char smdyn[];
    int* ssel_s = (int*)(smdyn + NSTAGE * BUFSZ);

    const int bf = blockIdx.y;
    const int b  = bf / FF;
    const int qt = blockIdx.x / HH;
    const int h  = blockIdx.x % HH;
    const int tid  = threadIdx.x;
    const int w    = tid >> 5;
    const int lane = tid & 31;
    const int g4 = lane >> 2;
    const int tg = lane & 3;
    const int woff = w * 32;
    const bool wactive = (qt * 128 + woff) < HW;   // warp has >=1 valid q row
    uint32_t smb[NSTAGE];
    #pragma unroll
    for (int s = 0; s < NSTAGE; s++) smb[s] = s2u(smdyn + s * BUFSZ);

    if (tid < TS) ssel_s[tid] = g_sel[bf * TS + tid];

    const __half* qh = g_qh + (size_t)bf * HW * DIM + h * HD;
    const __half* kh = g_kh + (size_t)b * FF * HW * DIM + h * HD;
    const __half* vh = g_vh + (size_t)b * FF * HW * DIM + h * HD;

    // ---- stage Q (128 rows x 64 dims fp16) into buf0, rows clamped ----
    #pragma unroll
    for (int it = 0; it < 8; it++) {
        int i = tid + it * 128;
        int r = i >> 3, c = i & 7;
        int qr = qt * 128 + r;
        if (qr > HW - 1) qr = HW - 1;
        uint4 d4 = *(const uint4*)(qh + (size_t)qr * DIM + c * 8);
        *(uint4*)(smdyn + r * KVSTRIDE + c * 16) = d4;
    }
    __syncthreads();

    // ldmatrix lane-address components
    const int r8 = lane & 7;
    const int e1 = ((lane >> 3) & 1) << 3;
    const int e2 = ((lane >> 4) & 1) << 3;

    // ---- Q A-fragments resident in registers for the whole kernel ----
    uint32_t qa[2][4][4];
    #pragma unroll
    for (int j = 0; j < 2; j++)
        #pragma unroll
        for (int kb = 0; kb < 4; kb++)
            ldm_x4(smb[0] + (uint32_t)((woff + j*16 + e1 + r8) * KVSTRIDE + (kb*16 + e2) * 2),
                   qa[j][kb]);
    __syncthreads();

    float o[2][8][4];
    #pragma unroll
    for (int j = 0; j < 2; j++)
        #pragma unroll
        for (int n = 0; n < 8; n++)
            #pragma unroll
            for (int c = 0; c < 4; c++) o[j][n][c] = 0.f;
    float lsum[2][2] = {{0.f,0.f},{0.f,0.f}};

    // prologue: stage tiles 0 and 1
    stage_kv(smb[0], kh, vh, ssel_s, 0, tid);
    CP_COMMIT();
    stage_kv(smb[1], kh, vh, ssel_s, NT, tid);
    CP_COMMIT();

    int buf = 0;
    for (int t = 0; t < NTILES; t++) {
        CP_WAIT1();           // tile t's group complete (only t+1 may be pending)
        __syncthreads();      // publish tile t; retire all reads of tile t-1

        // stage t+2 into the buffer vacated by t-1
        if (t + 2 < NTILES)
            stage_kv(smb[(buf + 2) % NSTAGE], kh, vh, ssel_s, (t + 2) * NT, tid);
        CP_COMMIT();

        const uint32_t kvb = smb[buf];
        buf = (buf + 1) % NSTAGE;

        if (!wactive) continue;   // warp-uniform: no valid q rows, skip compute

        const int kbase = t * NT;
        const bool edge = (kbase + NT > NKEY);

        // ---- process the 64-key tile as two 32-key halves ----
        #pragma unroll
        for (int nh = 0; nh < 2; nh++) {
            const int koff = nh * 32;

            // ---- MMA1: S(32x32 per warp) = Q @ K_half^T ----
            float s[2][4][4];
            #pragma unroll
            for (int j = 0; j < 2; j++)
                #pragma unroll
                for (int n = 0; n < 4; n++)
                    #pragma unroll
                    for (int c = 0; c < 4; c++) s[j][n][c] = 0.f;

            #pragma unroll
            for (int kb = 0; kb < 4; kb++) {
                #pragma unroll
                for (int nbp = 0; nbp < 2; nbp++) {
                    uint32_t r4[4];
                    ldm_x4(kvb + (uint32_t)((koff + nbp*16 + e2 + r8) * KVSTRIDE
                                            + (kb*16 + e1) * 2), r4);
                    mma16816(s[0][2*nbp],   qa[0][kb], r4[0], r4[1]);
                    mma16816(s[0][2*nbp+1], qa[0][kb], r4[2], r4[3]);
                    mma16816(s[1][2*nbp],   qa[1][kb], r4[0], r4[1]);
                    mma16816(s[1][2*nbp+1], qa[1][kb], r4[2], r4[3]);
                }
            }

            // ---- P = 2^S; pack C-frag -> A-frag ----
            uint32_t pa[2][2][4];
            #pragma unroll
            for (int j = 0; j < 2; j++) {
                #pragma unroll
                for (int nb = 0; nb < 4; nb++) {
                    float p0 = ex2(s[j][nb][0]);
                    float p1 = ex2(s[j][nb][1]);
                    float p2 = ex2(s[j][nb][2]);
                    float p3 = ex2(s[j][nb][3]);
                    if (edge) {
                        int c = kbase + koff + nb * 8 + 2 * tg;
                        if (c     >= NKEY) { p0 = 0.f; p2 = 0.f; }
                        if (c + 1 >= NKEY) { p1 = 0.f; p3 = 0.f; }
                    }
                    lsum[j][0] += p0 + p1;
                    lsum[j][1] += p2 + p3;
                    pa[j][nb >> 1][(nb & 1) * 2 + 0] = h2bits(p0, p1);
                    pa[j][nb >> 1][(nb & 1) * 2 + 1] = h2bits(p2, p3);
                }
            }

            // ---- MMA2: O += P_half @ V_half ----
            #pragma unroll
            for (int kc = 0; kc < 2; kc++) {
                #pragma unroll
                for (int np = 0; np < 4; np++) {
                    uint32_t r4[4];
                    ldm_x4_t(kvb + (uint32_t)((64 + koff + kc*16 + e1 + r8) * KVSTRIDE
                                              + (np*16 + e2) * 2), r4);
                    mma16816(o[0][2*np],   pa[0][kc], r4[0], r4[1]);
                    mma16816(o[0][2*np+1], pa[0][kc], r4[2], r4[3]);
                    mma16816(o[1][2*np],   pa[1][kc], r4[0], r4[1]);
                    mma16816(o[1][2*np+1], pa[1][kc], r4[2], r4[3]);
                }
            }
        }
    }

    if (!wactive) return;

    // ---- epilogue: quad-reduce row sums, normalize, store ----
    float inv[2][2];
    #pragma unroll
    for (int j = 0; j < 2; j++)
        #pragma unroll
        for (int d = 0; d < 2; d++) {
            float lv = lsum[j][d];
            lv += __shfl_xor_sync(0xffffffffu, lv, 1);
            lv += __shfl_xor_sync(0xffffffffu, lv, 2);
            inv[j][d] = 1.0f / lv;
        }

    #pragma unroll
    for (int j = 0; j < 2; j++) {
        int r0 = qt * 128 + woff + j * 16 + g4;
        int r1 = r0 + 8;
        #pragma unroll
        for (int nb = 0; nb < 8; nb++) {
            int col = h * HD + nb * 8 + 2 * tg;
            if (r0 < HW) {
                float2 wv;
                wv.x = o[j][nb][0] * inv[j][0];
                wv.y = o[j][nb][1] * inv[j][0];
                *(float2*)(out + ((size_t)bf * HW + r0) * DIM + col) = wv;
            }
            if (r1 < HW) {
                float2 wv;
                wv.x = o[j][nb][2] * inv[j][1];
                wv.y = o[j][nb][3] * inv[j][1];
                *(float2*)(out + ((size_t)bf * HW + r1) * DIM + col) = wv;
            }
        }
    }
}

// ---------------------------------------------------------------------------
extern "C" void kernel_launch(void* const* d_in, const int* in_sizes, int n_in,
                              void* d_out, int out_size)
{
    const float* q   = (const float*)d_in[0];
    const float* k   = (const float*)d_in[1];
    const float* v   = (const float*)d_in[2];
    const int*   cam = (const int*)d_in[3];
    float* out = (float*)d_out;

    (void)in_sizes; (void)n_in; (void)out_size;

    cudaFuncSetAttribute(attn_kernel,
                         cudaFuncAttributeMaxDynamicSharedMemorySize, SMEM_SZ);

    dim3 gcvt(BB * FF * 3, 3, 2);
    cvtall_kernel<<<gcvt, 128>>>(q, k, v);

    sel_kernel<<<BB * FF, 64>>>(cam);

    dim3 gattn(QT * HH, BB * FF);
    attn_kernel<<<gattn, 128, SMEM_SZ>>>(out);
}

// round 15
// speedup vs baseline: 1.0220x; 1.0220x over previous
#include <cuda_runtime.h>
#include <cuda_fp16.h>
#include <cstdint>
#include <cstddef>

// Problem constants
#define BB 2
#define FF 42
#define HW 390
#define HH 12
#define HD 64
#define DIM 768
#define TF 21
#define TOPK 5
#define CH 5
#define TS 10
#define NKEY 3900
#define NT 64
#define NTILES 61
#define QT 4
#define NELEM (BB*FF*HW*DIM)      // 25,159,680
#define RHALF 195                 // HW/2 rows per cvt chunk
// 0.125 * log2(e) folded into Q at conversion
#define QSCL 0.18033688011112042f

#define KVSTRIDE 144
#define BUFSZ (128*KVSTRIDE)      // 18432 B per stage
#define NSTAGE 3
#define SMEM_SZ (NSTAGE*BUFSZ + 64)

// fp16 copies of inputs (scratch device globals)
__device__ __half g_qh[NELEM];
__device__ __half g_kh[NELEM];
__device__ __half g_vh[NELEM];
__device__ float  g_qrepr2[2*BB*FF*DIM];   // partial row sums (2 halves)
__device__ float  g_krepr2[2*BB*FF*DIM];
__device__ int    g_sel[BB*FF*TS];

// ---------------------------------------------------------------------------
// PTX helpers (sm_80-level only — target is plain sm_100)
// ---------------------------------------------------------------------------
__device__ __forceinline__ uint32_t s2u(const void* p){
    uint32_t a;
    asm("{ .reg .u64 t; cvta.to.shared.u64 t, %1; cvt.u32.u64 %0, t; }":"=r"(a):"l"(p));
    return a;
}
__device__ __forceinline__ void ldm_x4(uint32_t addr, uint32_t* r){
    asm volatile("ldmatrix.sync.aligned.m8n8.x4.shared.b16 {%0,%1,%2,%3}, [%4];"
        : "=r"(r[0]),"=r"(r[1]),"=r"(r[2]),"=r"(r[3]) : "r"(addr));
}
__device__ __forceinline__ void ldm_x4_t(uint32_t addr, uint32_t* r){
    asm volatile("ldmatrix.sync.aligned.m8n8.x4.trans.shared.b16 {%0,%1,%2,%3}, [%4];"
        : "=r"(r[0]),"=r"(r[1]),"=r"(r[2]),"=r"(r[3]) : "r"(addr));
}
__device__ __forceinline__ void mma16816(float* d, const uint32_t* a,
                                         uint32_t b0, uint32_t b1){
    asm volatile("mma.sync.aligned.m16n8k16.row.col.f32.f16.f16.f32 "
        "{%0,%1,%2,%3}, {%4,%5,%6,%7}, {%8,%9}, {%0,%1,%2,%3};"
        : "+f"(d[0]),"+f"(d[1]),"+f"(d[2]),"+f"(d[3])
        : "r"(a[0]),"r"(a[1]),"r"(a[2]),"r"(a[3]), "r"(b0),"r"(b1));
}
__device__ __forceinline__ float ex2(float x){
    float r; asm("ex2.approx.ftz.f32 %0, %1;" : "=f"(r) : "f"(x)); return r;
}
__device__ __forceinline__ uint32_t h2bits(float lo, float hi){
    __half2 h = __floats2half2_rn(lo, hi);
    return *reinterpret_cast<uint32_t*>(&h);
}
#define CP_ASYNC16(sm, gp) \
    asm volatile("cp.async.cg.shared.global [%0], [%1], 16;" :: "r"(sm), "l"(gp))
#define CP_COMMIT() asm volatile("cp.async.commit_group;" ::: "memory")
#define CP_WAIT1()  asm volatile("cp.async.wait_group 1;" ::: "memory")

// ---------------------------------------------------------------------------
// Kernel 0: fused fp32->fp16 conversion for q,k,v + partial means for q,k
// grid (BB*FF*3, 3, 2): x = bf*3+dimchunk(256 dims), y = 0:q 1:k 2:v,
// z = row half. block = 128. Each thread: 2 adjacent dims, 195 rows.
// ---------------------------------------------------------------------------
__global__ void cvtall_kernel(const float* __restrict__ q,
                              const float* __restrict__ k,
                              const float* __restrict__ v)
{
    int arr = blockIdx.y;
    int rc  = blockIdx.z;
    const float* src = (arr == 0) ? q : (arr == 1) ? k : v;
    __half* dst = (arr == 0) ? g_qh : (arr == 1) ? g_kh : g_vh;
    float scl = (arr == 0) ? QSCL : 1.0f;
    int bf = blockIdx.x / 3;
    int dc = blockIdx.x % 3;
    int d0 = dc * 256 + threadIdx.x * 2;
    size_t base = (size_t)bf * HW * DIM + (size_t)rc * RHALF * DIM + d0;
    float s0 = 0.f, s1 = 0.f;
    #pragma unroll 5
    for (int r = 0; r < RHALF; r++) {
        float2 x = *(const float2*)(src + base + (size_t)r * DIM);
        s0 += x.x; s1 += x.y;
        *(__half2*)(dst + base + (size_t)r * DIM) =
            __floats2half2_rn(x.x * scl, x.y * scl);
    }
    if (arr < 2) {
        float* mdst = arr ? g_krepr2 : g_qrepr2;
        size_t mo = (size_t)(rc * BB * FF + bf) * DIM + d0;
        mdst[mo]     = s0;
        mdst[mo + 1] = s1;
    }
}

// ---------------------------------------------------------------------------
// Kernel 2: sim row + top-k + selection  (sums the two mean partials; sim is
// scaled by a positive constant vs reference -> identical top-k ordering)
// ---------------------------------------------------------------------------
__global__ void sel_kernel(const int* __restrict__ cam)
{
    int bf = blockIdx.x;
    int b = bf / FF, f = bf % FF;
    __shared__ float qs[DIM];
    __shared__ float sim[FF];

    for (int d = threadIdx.x; d < DIM; d += blockDim.x)
        qs[d] = g_qrepr2[bf * DIM + d]
              + g_qrepr2[(BB * FF + bf) * DIM + d];
    __syncthreads();

    for (int g = threadIdx.x; g < FF; g += blockDim.x) {
        const float* kr0 = &g_krepr2[(b * FF + g) * DIM];
        const float* kr1 = &g_krepr2[(BB * FF + b * FF + g) * DIM];
        float s = 0.f;
        #pragma unroll 4
        for (int d = 0; d < DIM; d++) s += qs[d] * (kr0[d] + kr1[d]);
        sim[g] = s;
    }
    __syncthreads();

    if (threadIdx.x == 0) {
        int sel[TS];
        int start = f - 2;
        if (start < 0)  start = 0;
        if (start > 16) start = 16;
        #pragma unroll
        for (int j = 0; j < CH; j++) sel[j] = start + j;

        if (f < TF) {
            #pragma unroll
            for (int j = 0; j < TOPK; j++) sel[CH + j] = cam[f * TOPK + j];
        } else {
            bool used[FF - TF];
            for (int g = 0; g < FF - TF; g++) used[g] = false;
            for (int j = 0; j < TOPK; j++) {
                float best = -3.4e38f; int bi = 0;
                for (int g = 0; g < FF - TF; g++) {
                    if (!used[g] && sim[TF + g] > best) { best = sim[TF + g]; bi = g; }
                }
                used[bi] = true;
                sel[CH + j] = bi + TF;
            }
        }
        for (int j = 0; j < TS; j++) g_sel[bf * TS + j] = sel[j];
    }
}

// ---------------------------------------------------------------------------
// K/V tile stage via cp.async: rows 0..63 = K, 64..127 = V, stride 144B
// 256 threads: 4 iterations cover 1024 16B transfers.
// ---------------------------------------------------------------------------
__device__ __forceinline__ void stage_kv(uint32_t dstb,
                                         const __half* kh, const __half* vh,
                                         const int* ssel, int kbase, int tid)
{
    #pragma unroll
    for (int it = 0; it < 4; it++) {
        int i = tid + it * 256;
        int r = i >> 3, c = i & 7;
        int kk = kbase + (r & 63);
        if (kk > NKEY - 1) kk = NKEY - 1;
        int fr = kk / HW;
        int g  = ssel[fr];
        const __half* src = (r < 64 ? kh : vh)
            + (size_t)(g * HW + (kk - fr * HW)) * DIM + c * 8;
        CP_ASYNC16(dstb + (uint32_t)(r * KVSTRIDE + c * 16), src);
    }
}

// ---------------------------------------------------------------------------
// Kernel 3: fp16 mma.sync flash attention
// grid = (QT*HH, BB*FF), block = 256 (8 warps, warp owns 16 q rows).
// CTA M=128 preserved (staging amortization unchanged vs the 1409us config);
// LDSM doubles (L1 41.9% -> ~80%), warps/SM 12 -> 16 (2 CTAs/SM, reg cap 128).
// 3-stage cp.async ring, fp32-ex2 softmax, 32-key halves.
// ---------------------------------------------------------------------------
__global__ __launch_bounds__(256, 2)
void attn_kernel(float* __restrict__ out)
{
    extern __shared__ __align__(16) unsigned char smdyn[];
    int* ssel_s = (int*)(smdyn + NSTAGE * BUFSZ);

    const int bf = blockIdx.y;
    const int b  = bf / FF;
    const int qt = blockIdx.x / HH;
    const int h  = blockIdx.x % HH;
    const int tid  = threadIdx.x;
    const int w    = tid >> 5;
    const int lane = tid & 31;
    const int g4 = lane >> 2;
    const int tg = lane & 3;
    const int woff = w * 16;                       // warp owns 16 q rows
    const bool wactive = (qt * 128 + woff) < HW;   // warp has >=1 valid q row
    const uint32_t smb0 = s2u(smdyn);

    if (tid < TS) ssel_s[tid] = g_sel[bf * TS + tid];

    const __half* qh = g_qh + (size_t)bf * HW * DIM + h * HD;
    const __half* kh = g_kh + (size_t)b * FF * HW * DIM + h * HD;
    const __half* vh = g_vh + (size_t)b * FF * HW * DIM + h * HD;

    // ---- stage Q (128 rows x 64 dims fp16) into buf0, rows clamped ----
    #pragma unroll
    for (int it = 0; it < 4; it++) {
        int i = tid + it * 256;
        int r = i >> 3, c = i & 7;
        int qr = qt * 128 + r;
        if (qr > HW - 1) qr = HW - 1;
        uint4 d4 = *(const uint4*)(qh + (size_t)qr * DIM + c * 8);
        *(uint4*)(smdyn + r * KVSTRIDE + c * 16) = d4;
    }
    __syncthreads();

    // ldmatrix lane-address components
    const int r8 = lane & 7;
    const int e1 = ((lane >> 3) & 1) << 3;
    const int e2 = ((lane >> 4) & 1) << 3;

    // ---- Q A-fragments (16 rows) resident in registers ----
    uint32_t qa[4][4];
    #pragma unroll
    for (int kb = 0; kb < 4; kb++)
        ldm_x4(smb0 + (uint32_t)((woff + e1 + r8) * KVSTRIDE + (kb*16 + e2) * 2),
               qa[kb]);
    __syncthreads();

    float o[8][4];
    #pragma unroll
    for (int n = 0; n < 8; n++)
        #pragma unroll
        for (int c = 0; c < 4; c++) o[n][c] = 0.f;
    float lsum[2] = {0.f, 0.f};

    // prologue: stage tiles 0 and 1
    stage_kv(smb0, kh, vh, ssel_s, 0, tid);
    CP_COMMIT();
    stage_kv(smb0 + BUFSZ, kh, vh, ssel_s, NT, tid);
    CP_COMMIT();

    int buf = 0;
    for (int t = 0; t < NTILES; t++) {
        CP_WAIT1();           // tile t's group complete (only t+1 may be pending)
        __syncthreads();      // publish tile t; retire all reads of tile t-1

        // stage t+2 into the buffer vacated by t-1
        if (t + 2 < NTILES) {
            int b2 = buf + 2; if (b2 >= NSTAGE) b2 -= NSTAGE;
            stage_kv(smb0 + b2 * BUFSZ, kh, vh, ssel_s, (t + 2) * NT, tid);
        }
        CP_COMMIT();

        const uint32_t kvb = smb0 + buf * BUFSZ;
        buf = buf + 1; if (buf >= NSTAGE) buf = 0;

        if (!wactive) continue;   // warp-uniform: no valid q rows, skip compute

        const int kbase = t * NT;
        const bool edge = (kbase + NT > NKEY);

        // ---- process the 64-key tile as two 32-key halves ----
        #pragma unroll
        for (int nh = 0; nh < 2; nh++) {
            const int koff = nh * 32;

            // ---- MMA1: S(16x32 per warp) = Q @ K_half^T ----
            float s[4][4];
            #pragma unroll
            for (int n = 0; n < 4; n++)
                #pragma unroll
                for (int c = 0; c < 4; c++) s[n][c] = 0.f;

            #pragma unroll
            for (int kb = 0; kb < 4; kb++) {
                #pragma unroll
                for (int nbp = 0; nbp < 2; nbp++) {
                    uint32_t r4[4];
                    ldm_x4(kvb + (uint32_t)((koff + nbp*16 + e2 + r8) * KVSTRIDE
                                            + (kb*16 + e1) * 2), r4);
                    mma16816(s[2*nbp],   qa[kb], r4[0], r4[1]);
                    mma16816(s[2*nbp+1], qa[kb], r4[2], r4[3]);
                }
            }

            // ---- P = 2^S; pack C-frag -> A-frag ----
            uint32_t pa[2][4];
            #pragma unroll
            for (int nb = 0; nb < 4; nb++) {
                float p0 = ex2(s[nb][0]);
                float p1 = ex2(s[nb][1]);
                float p2 = ex2(s[nb][2]);
                float p3 = ex2(s[nb][3]);
                if (edge) {
                    int c = kbase + koff + nb * 8 + 2 * tg;
                    if (c     >= NKEY) { p0 = 0.f; p2 = 0.f; }
                    if (c + 1 >= NKEY) { p1 = 0.f; p3 = 0.f; }
                }
                lsum[0] += p0 + p1;
                lsum[1] += p2 + p3;
                pa[nb >> 1][(nb & 1) * 2 + 0] = h2bits(p0, p1);
                pa[nb >> 1][(nb & 1) * 2 + 1] = h2bits(p2, p3);
            }

            // ---- MMA2: O += P_half @ V_half ----
            #pragma unroll
            for (int kc = 0; kc < 2; kc++) {
                #pragma unroll
                for (int np = 0; np < 4; np++) {
                    uint32_t r4[4];
                    ldm_x4_t(kvb + (uint32_t)((64 + koff + kc*16 + e1 + r8) * KVSTRIDE
                                              + (np*16 + e2) * 2), r4);
                    mma16816(o[2*np],   pa[kc], r4[0], r4[1]);
                    mma16816(o[2*np+1], pa[kc], r4[2], r4[3]);
                }
            }
        }
    }

    if (!wactive) return;

    // ---- epilogue: quad-reduce row sums, normalize, store ----
    float inv[2];
    #pragma unroll
    for (int d = 0; d < 2; d++) {
        float lv = lsum[d];
        lv += __shfl_xor_sync(0xffffffffu, lv, 1);
        lv += __shfl_xor_sync(0xffffffffu, lv, 2);
        inv[d] = 1.0f / lv;
    }

    {
        int r0 = qt * 128 + woff + g4;
        int r1 = r0 + 8;
        #pragma unroll
        for (int nb = 0; nb < 8; nb++) {
            int col = h * HD + nb * 8 + 2 * tg;
            if (r0 < HW) {
                float2 wv;
                wv.x = o[nb][0] * inv[0];
                wv.y = o[nb][1] * inv[0];
                *(float2*)(out + ((size_t)bf * HW + r0) * DIM + col) = wv;
            }
            if (r1 < HW) {
                float2 wv;
                wv.x = o[nb][2] * inv[1];
                wv.y = o[nb][3] * inv[1];
                *(float2*)(out + ((size_t)bf * HW + r1) * DIM + col) = wv;
            }
        }
    }
}

// ---------------------------------------------------------------------------
extern "C" void kernel_launch(void* const* d_in, const int* in_sizes, int n_in,
                              void* d_out, int out_size)
{
    const float* q   = (const float*)d_in[0];
    const float* k   = (const float*)d_in[1];
    const float* v   = (const float*)d_in[2];
    const int*   cam = (const int*)d_in[3];
    float* out = (float*)d_out;

    (void)in_sizes; (void)n_in; (void)out_size;

    cudaFuncSetAttribute(attn_kernel,
                         cudaFuncAttributeMaxDynamicSharedMemorySize, SMEM_SZ);

    dim3 gcvt(BB * FF * 3, 3, 2);
    cvtall_kernel<<<gcvt, 128>>>(q, k, v);

    sel_kernel<<<BB * FF, 64>>>(cam);

    dim3 gattn(QT * HH, BB * FF);
    attn_kernel<<<gattn, 256, SMEM_SZ>>>(out);
}

// round 16
// speedup vs baseline: 1.0513x; 1.0287x over previous
#include <cuda_runtime.h>
#include <cuda_fp16.h>
#include <cstdint>
#include <cstddef>

// Problem constants
#define BB 2
#define FF 42
#define HW 390
#define HH 12
#define HD 64
#define DIM 768
#define TF 21
#define TOPK 5
#define CH 5
#define TS 10
#define NKEY 3900
#define NT 128
#define NTILES 31                 // ceil(3900/128)
#define QT 4
#define NELEM (BB*FF*HW*DIM)      // 25,159,680
#define RHALF 195                 // HW/2 rows per cvt chunk
// 0.125 * log2(e) folded into Q at conversion
#define QSCL 0.18033688011112042f

#define KVSTRIDE 144
#define BUFSZ (256*KVSTRIDE)      // 36864 B per stage (128 K rows + 128 V rows)
#define NSTAGE 2
#define SMEM_SZ (NSTAGE*BUFSZ + 64)

// fp16 copies of inputs (scratch device globals)
__device__ __half g_qh[NELEM];
__device__ __half g_kh[NELEM];
__device__ __half g_vh[NELEM];
__device__ float  g_qrepr2[2*BB*FF*DIM];   // partial row sums (2 halves)
__device__ float  g_krepr2[2*BB*FF*DIM];
__device__ int    g_sel[BB*FF*TS];

// ---------------------------------------------------------------------------
// PTX helpers (sm_80-level only — target is plain sm_100)
// ---------------------------------------------------------------------------
__device__ __forceinline__ uint32_t s2u(const void* p){
    uint32_t a;
    asm("{ .reg .u64 t; cvta.to.shared.u64 t, %1; cvt.u32.u64 %0, t; }":"=r"(a):"l"(p));
    return a;
}
__device__ __forceinline__ void ldm_x4(uint32_t addr, uint32_t* r){
    asm volatile("ldmatrix.sync.aligned.m8n8.x4.shared.b16 {%0,%1,%2,%3}, [%4];"
        : "=r"(r[0]),"=r"(r[1]),"=r"(r[2]),"=r"(r[3]) : "r"(addr));
}
__device__ __forceinline__ void ldm_x4_t(uint32_t addr, uint32_t* r){
    asm volatile("ldmatrix.sync.aligned.m8n8.x4.trans.shared.b16 {%0,%1,%2,%3}, [%4];"
        : "=r"(r[0]),"=r"(r[1]),"=r"(r[2]),"=r"(r[3]) : "r"(addr));
}
__device__ __forceinline__ void mma16816(float* d, const uint32_t* a,
                                         uint32_t b0, uint32_t b1){
    asm volatile("mma.sync.aligned.m16n8k16.row.col.f32.f16.f16.f32 "
        "{%0,%1,%2,%3}, {%4,%5,%6,%7}, {%8,%9}, {%0,%1,%2,%3};"
        : "+f"(d[0]),"+f"(d[1]),"+f"(d[2]),"+f"(d[3])
        : "r"(a[0]),"r"(a[1]),"r"(a[2]),"r"(a[3]), "r"(b0),"r"(b1));
}
__device__ __forceinline__ float ex2(float x){
    float r; asm("ex2.approx.ftz.f32 %0, %1;" : "=f"(r) : "f"(x)); return r;
}
__device__ __forceinline__ uint32_t h2bits(float lo, float hi){
    __half2 h = __floats2half2_rn(lo, hi);
    return *reinterpret_cast<uint32_t*>(&h);
}
#define CP_ASYNC16(sm, gp) \
    asm volatile("cp.async.cg.shared.global [%0], [%1], 16;" :: "r"(sm), "l"(gp))
#define CP_COMMIT() asm volatile("cp.async.commit_group;" ::: "memory")
#define CP_WAIT0()  asm volatile("cp.async.wait_group 0;" ::: "memory")

// ---------------------------------------------------------------------------
// Kernel 0: fused fp32->fp16 conversion for q,k,v + partial means for q,k
// grid (BB*FF*3, 3, 2): x = bf*3+dimchunk(256 dims), y = 0:q 1:k 2:v,
// z = row half. block = 128. Each thread: 2 adjacent dims, 195 rows.
// ---------------------------------------------------------------------------
__global__ void cvtall_kernel(const float* __restrict__ q,
                              const float* __restrict__ k,
                              const float* __restrict__ v)
{
    int arr = blockIdx.y;
    int rc  = blockIdx.z;
    const float* src = (arr == 0) ? q : (arr == 1) ? k : v;
    __half* dst = (arr == 0) ? g_qh : (arr == 1) ? g_kh : g_vh;
    float scl = (arr == 0) ? QSCL : 1.0f;
    int bf = blockIdx.x / 3;
    int dc = blockIdx.x % 3;
    int d0 = dc * 256 + threadIdx.x * 2;
    size_t base = (size_t)bf * HW * DIM + (size_t)rc * RHALF * DIM + d0;
    float s0 = 0.f, s1 = 0.f;
    #pragma unroll 5
    for (int r = 0; r < RHALF; r++) {
        float2 x = *(const float2*)(src + base + (size_t)r * DIM);
        s0 += x.x; s1 += x.y;
        *(__half2*)(dst + base + (size_t)r * DIM) =
            __floats2half2_rn(x.x * scl, x.y * scl);
    }
    if (arr < 2) {
        float* mdst = arr ? g_krepr2 : g_qrepr2;
        size_t mo = (size_t)(rc * BB * FF + bf) * DIM + d0;
        mdst[mo]     = s0;
        mdst[mo + 1] = s1;
    }
}

// ---------------------------------------------------------------------------
// Kernel 2: sim row + top-k + selection  (sums the two mean partials; sim is
// scaled by a positive constant vs reference -> identical top-k ordering)
// ---------------------------------------------------------------------------
__global__ void sel_kernel(const int* __restrict__ cam)
{
    int bf = blockIdx.x;
    int b = bf / FF, f = bf % FF;
    __shared__ float qs[DIM];
    __shared__ float sim[FF];

    for (int d = threadIdx.x; d < DIM; d += blockDim.x)
        qs[d] = g_qrepr2[bf * DIM + d]
              + g_qrepr2[(BB * FF + bf) * DIM + d];
    __syncthreads();

    for (int g = threadIdx.x; g < FF; g += blockDim.x) {
        const float* kr0 = &g_krepr2[(b * FF + g) * DIM];
        const float* kr1 = &g_krepr2[(BB * FF + b * FF + g) * DIM];
        float s = 0.f;
        #pragma unroll 4
        for (int d = 0; d < DIM; d++) s += qs[d] * (kr0[d] + kr1[d]);
        sim[g] = s;
    }
    __syncthreads();

    if (threadIdx.x == 0) {
        int sel[TS];
        int start = f - 2;
        if (start < 0)  start = 0;
        if (start > 16) start = 16;
        #pragma unroll
        for (int j = 0; j < CH; j++) sel[j] = start + j;

        if (f < TF) {
            #pragma unroll
            for (int j = 0; j < TOPK; j++) sel[CH + j] = cam[f * TOPK + j];
        } else {
            bool used[FF - TF];
            for (int g = 0; g < FF - TF; g++) used[g] = false;
            for (int j = 0; j < TOPK; j++) {
                float best = -3.4e38f; int bi = 0;
                for (int g = 0; g < FF - TF; g++) {
                    if (!used[g] && sim[TF + g] > best) { best = sim[TF + g]; bi = g; }
                }
                used[bi] = true;
                sel[CH + j] = bi + TF;
            }
        }
        for (int j = 0; j < TS; j++) g_sel[bf * TS + j] = sel[j];
    }
}

// ---------------------------------------------------------------------------
// K/V tile stage via cp.async: rows 0..127 = K, 128..255 = V, stride 144B
// 256 threads: 8 iterations cover 2048 16B transfers.
// ---------------------------------------------------------------------------
__device__ __forceinline__ void stage_kv(uint32_t dstb,
                                         const __half* kh, const __half* vh,
                                         const int* ssel, int kbase, int tid)
{
    #pragma unroll
    for (int it = 0; it < 8; it++) {
        int i = tid + it * 256;
        int r = i >> 3, c = i & 7;
        int kk = kbase + (r & 127);
        if (kk > NKEY - 1) kk = NKEY - 1;
        int fr = kk / HW;
        int g  = ssel[fr];
        const __half* src = (r < 128 ? kh : vh)
            + (size_t)(g * HW + (kk - fr * HW)) * DIM + c * 8;
        CP_ASYNC16(dstb + (uint32_t)(r * KVSTRIDE + c * 16), src);
    }
}

// ---------------------------------------------------------------------------
// Kernel 3: fp16 mma.sync flash attention
// grid = (QT*HH, BB*FF), block = 256 (8 warps, warp owns 16 q rows).
// NT=128 2-stage ring on the R15 8-warp base: halves barrier count (61->31)
// and ring overhead; LDSM/MMA/reg structure unchanged (32-key chunks).
// ---------------------------------------------------------------------------
__global__ __launch_bounds__(256, 2)
void attn_kernel(float* __restrict__ out)
{
    extern __shared__ __align__(16) unsigned char smdyn[];
    int* ssel_s = (int*)(smdyn + NSTAGE * BUFSZ);

    const int bf = blockIdx.y;
    const int b  = bf / FF;
    const int qt = blockIdx.x / HH;
    const int h  = blockIdx.x % HH;
    const int tid  = threadIdx.x;
    const int w    = tid >> 5;
    const int lane = tid & 31;
    const int g4 = lane >> 2;
    const int tg = lane & 3;
    const int woff = w * 16;                       // warp owns 16 q rows
    const bool wactive = (qt * 128 + woff) < HW;   // warp has >=1 valid q row
    const uint32_t smb0 = s2u(smdyn);

    if (tid < TS) ssel_s[tid] = g_sel[bf * TS + tid];

    const __half* qh = g_qh + (size_t)bf * HW * DIM + h * HD;
    const __half* kh = g_kh + (size_t)b * FF * HW * DIM + h * HD;
    const __half* vh = g_vh + (size_t)b * FF * HW * DIM + h * HD;

    // ---- stage Q (128 rows x 64 dims fp16) into buf0, rows clamped ----
    #pragma unroll
    for (int it = 0; it < 4; it++) {
        int i = tid + it * 256;
        int r = i >> 3, c = i & 7;
        int qr = qt * 128 + r;
        if (qr > HW - 1) qr = HW - 1;
        uint4 d4 = *(const uint4*)(qh + (size_t)qr * DIM + c * 8);
        *(uint4*)(smdyn + r * KVSTRIDE + c * 16) = d4;
    }
    __syncthreads();

    // ldmatrix lane-address components
    const int r8 = lane & 7;
    const int e1 = ((lane >> 3) & 1) << 3;
    const int e2 = ((lane >> 4) & 1) << 3;

    // ---- Q A-fragments (16 rows) resident in registers ----
    uint32_t qa[4][4];
    #pragma unroll
    for (int kb = 0; kb < 4; kb++)
        ldm_x4(smb0 + (uint32_t)((woff + e1 + r8) * KVSTRIDE + (kb*16 + e2) * 2),
               qa[kb]);
    __syncthreads();

    float o[8][4];
    #pragma unroll
    for (int n = 0; n < 8; n++)
        #pragma unroll
        for (int c = 0; c < 4; c++) o[n][c] = 0.f;
    float lsum[2] = {0.f, 0.f};

    // prologue: stage tile 0 into buf0 (Q already consumed into registers)
    stage_kv(smb0, kh, vh, ssel_s, 0, tid);
    CP_COMMIT();

    for (int t = 0; t < NTILES; t++) {
        CP_WAIT0();           // tile t staged
        __syncthreads();      // publish tile t; retire reads of tile t-1

        // stage t+1 into the other buffer (vacated by t-1); overlaps compute(t)
        if (t + 1 < NTILES) {
            stage_kv(smb0 + ((t + 1) & 1) * BUFSZ, kh, vh, ssel_s,
                     (t + 1) * NT, tid);
            CP_COMMIT();
        }

        const uint32_t kvb = smb0 + (t & 1) * BUFSZ;

        if (!wactive) continue;   // warp-uniform: no valid q rows, skip compute

        const int kbase = t * NT;
        const bool edge = (kbase + NT > NKEY);

        // ---- process the 128-key tile as four 32-key chunks ----
        #pragma unroll
        for (int nh = 0; nh < 4; nh++) {
            const int koff = nh * 32;

            // ---- MMA1: S(16x32 per warp) = Q @ K_chunk^T ----
            float s[4][4];
            #pragma unroll
            for (int n = 0; n < 4; n++)
                #pragma unroll
                for (int c = 0; c < 4; c++) s[n][c] = 0.f;

            #pragma unroll
            for (int kb = 0; kb < 4; kb++) {
                #pragma unroll
                for (int nbp = 0; nbp < 2; nbp++) {
                    uint32_t r4[4];
                    ldm_x4(kvb + (uint32_t)((koff + nbp*16 + e2 + r8) * KVSTRIDE
                                            + (kb*16 + e1) * 2), r4);
                    mma16816(s[2*nbp],   qa[kb], r4[0], r4[1]);
                    mma16816(s[2*nbp+1], qa[kb], r4[2], r4[3]);
                }
            }

            // ---- P = 2^S; pack C-frag -> A-frag ----
            uint32_t pa[2][4];
            #pragma unroll
            for (int nb = 0; nb < 4; nb++) {
                float p0 = ex2(s[nb][0]);
                float p1 = ex2(s[nb][1]);
                float p2 = ex2(s[nb][2]);
                float p3 = ex2(s[nb][3]);
                if (edge) {
                    int c = kbase + koff + nb * 8 + 2 * tg;
                    if (c     >= NKEY) { p0 = 0.f; p2 = 0.f; }
                    if (c + 1 >= NKEY) { p1 = 0.f; p3 = 0.f; }
                }
                lsum[0] += p0 + p1;
                lsum[1] += p2 + p3;
                pa[nb >> 1][(nb & 1) * 2 + 0] = h2bits(p0, p1);
                pa[nb >> 1][(nb & 1) * 2 + 1] = h2bits(p2, p3);
            }

            // ---- MMA2: O += P_chunk @ V_chunk ----
            #pragma unroll
            for (int kc = 0; kc < 2; kc++) {
                #pragma unroll
                for (int np = 0; np < 4; np++) {
                    uint32_t r4[4];
                    ldm_x4_t(kvb + (uint32_t)((128 + koff + kc*16 + e1 + r8) * KVSTRIDE
                                              + (np*16 + e2) * 2), r4);
                    mma16816(o[2*np],   pa[kc], r4[0], r4[1]);
                    mma16816(o[2*np+1], pa[kc], r4[2], r4[3]);
                }
            }
        }
    }

    if (!wactive) return;

    // ---- epilogue: quad-reduce row sums, normalize, store ----
    float inv[2];
    #pragma unroll
    for (int d = 0; d < 2; d++) {
        float lv = lsum[d];
        lv += __shfl_xor_sync(0xffffffffu, lv, 1);
        lv += __shfl_xor_sync(0xffffffffu, lv, 2);
        inv[d] = 1.0f / lv;
    }

    {
        int r0 = qt * 128 + woff + g4;
        int r1 = r0 + 8;
        #pragma unroll
        for (int nb = 0; nb < 8; nb++) {
            int col = h * HD + nb * 8 + 2 * tg;
            if (r0 < HW) {
                float2 wv;
                wv.x = o[nb][0] * inv[0];
                wv.y = o[nb][1] * inv[0];
                *(float2*)(out + ((size_t)bf * HW + r0) * DIM + col) = wv;
            }
            if (r1 < HW) {
                float2 wv;
                wv.x = o[nb][2] * inv[1];
                wv.y = o[nb][3] * inv[1];
                *(float2*)(out + ((size_t)bf * HW + r1) * DIM + col) = wv;
            }
        }
    }
}

// ---------------------------------------------------------------------------
extern "C" void kernel_launch(void* const* d_in, const int* in_sizes, int n_in,
                              void* d_out, int out_size)
{
    const float* q   = (const float*)d_in[0];
    const float* k   = (const float*)d_in[1];
    const float* v   = (const float*)d_in[2];
    const int*   cam = (const int*)d_in[3];
    float* out = (float*)d_out;

    (void)in_sizes; (void)n_in; (void)out_size;

    cudaFuncSetAttribute(attn_kernel,
                         cudaFuncAttributeMaxDynamicSharedMemorySize, SMEM_SZ);

    dim3 gcvt(BB * FF * 3, 3, 2);
    cvtall_kernel<<<gcvt, 128>>>(q, k, v);

    sel_kernel<<<BB * FF, 64>>>(cam);

    dim3 gattn(QT * HH, BB * FF);
    attn_kernel<<<gattn, 256, SMEM_SZ>>>(out);
}